// round 10
// baseline (speedup 1.0000x reference)
#include <cstdint>
#include <cuda_runtime.h>
#include <cuda_bf16.h>
#include <mma.h>

using namespace nvcuda;

// Problem dims
#define B_   64
#define T_   1024
#define H_   512
#define M_   (B_ * T_)      // 65536 rows
#define L_   4
#define G3H  (3 * H_)       // 1536

// Weight pack offsets (elements)
#define OFF_WIN  0
#define OFF_WIH  (512*512)
#define OFF_WO1  (OFF_WIH + 4*1536*512)
#define OFF_WO2  (OFF_WO1 + 512*512)
#define WTOT     (OFF_WO2 + 512*512)

// ---------------- static device scratch (no runtime allocation) ----------------
__device__ float          g_gi[(size_t)M_ * G3H];       // 402 MB
__device__ __nv_bfloat16  g_aAh[(size_t)M_ * H_];       // activation pair buffer A
__device__ __nv_bfloat16  g_aAl[(size_t)M_ * H_];
__device__ __nv_bfloat16  g_aBh[(size_t)M_ * H_];       // activation pair buffer B
__device__ __nv_bfloat16  g_aBl[(size_t)M_ * H_];
__device__ __nv_bfloat16  g_wh[WTOT];                   // pre-split weights
__device__ __nv_bfloat16  g_wl[WTOT];
__device__ __nv_bfloat16  g_hbH[2 * B_ * H_];           // hidden state pair, double buffered
__device__ __nv_bfloat16  g_hbL[2 * B_ * H_];
__device__ int            g_bar[4 * 32];                // per-group barrier counters

// ---------------- helpers ----------------
__device__ __forceinline__ void split_bf16(float v, __nv_bfloat16& hi, __nv_bfloat16& lo) {
    hi = __float2bfloat16(v);
    lo = __float2bfloat16(v - __bfloat162float(hi));
}
__device__ __forceinline__ float fast_sigmoid(float x) {
    return __fdividef(1.0f, 1.0f + __expf(-x));
}
__device__ __forceinline__ float fast_tanh(float x) {
    float e = __expf(-2.0f * x);
    return __fdividef(1.0f - e, 1.0f + e);
}
__device__ __forceinline__ void cp_async16(void* dst, const void* src) {
    uint32_t d = (uint32_t)__cvta_generic_to_shared(dst);
    asm volatile("cp.async.cg.shared.global [%0], [%1], 16;" :: "r"(d), "l"(src));
}
__device__ __forceinline__ void cp_commit() { asm volatile("cp.async.commit_group;"); }
__device__ __forceinline__ void cp_wait0()  { asm volatile("cp.async.wait_group 0;"); }
__device__ __forceinline__ void cp_wait1()  { asm volatile("cp.async.wait_group 1;"); }

// =================================================================================
// split: fp32 -> bf16 hi/lo pair (vectorized)
// =================================================================================
__global__ __launch_bounds__(256)
void split_kernel(const float* __restrict__ in, __nv_bfloat16* __restrict__ hi,
                  __nv_bfloat16* __restrict__ lo, int n4)
{
    int i = blockIdx.x * 256 + threadIdx.x;
    if (i >= n4) return;
    float4 v = ((const float4*)in)[i];
    __nv_bfloat16 h0,l0,h1,l1,h2,l2,h3,l3;
    split_bf16(v.x, h0, l0); split_bf16(v.y, h1, l1);
    split_bf16(v.z, h2, l2); split_bf16(v.w, h3, l3);
    ((__nv_bfloat162*)hi)[2*i]   = __nv_bfloat162(h0, h1);
    ((__nv_bfloat162*)hi)[2*i+1] = __nv_bfloat162(h2, h3);
    ((__nv_bfloat162*)lo)[2*i]   = __nv_bfloat162(l0, l1);
    ((__nv_bfloat162*)lo)[2*i+1] = __nv_bfloat162(l2, l3);
}

// =================================================================================
// GEMM v2: C = act(A @ W^T + bias), A and W given as pre-split bf16 hi/lo pairs.
// Pure cp.async double-buffered pipeline; no conversion in the loop.
// Block 128x128x32, 8 warps (2x4), warp tile 64x32. Output fp32 or bf16 pair.
// =================================================================================
#define BM 128
#define BN 128
#define BK 32
#define GLD 40
#define TILE (128 * GLD)     // elems per smem sub-buffer
#define GEMM_SMEM (2 * 4 * TILE * 2)   // 81,920 B

template<int RELU, int OUTPAIR>
__global__ __launch_bounds__(256, 2)
void gemm2(const __nv_bfloat16* __restrict__ Ah, const __nv_bfloat16* __restrict__ Al,
           const __nv_bfloat16* __restrict__ Wh, const __nv_bfloat16* __restrict__ Wl,
           const float* __restrict__ bias,
           float* __restrict__ Cf,
           __nv_bfloat16* __restrict__ Ch, __nv_bfloat16* __restrict__ Cl,
           int M, int N, int K)
{
    extern __shared__ __nv_bfloat16 sm[];

    const int tid  = threadIdx.x;
    const int m0   = blockIdx.y * BM;
    const int n0   = blockIdx.x * BN;
    const int w    = tid >> 5;
    const int lane = tid & 31;
    const int wm   = w >> 2;
    const int wn   = w & 3;

    wmma::fragment<wmma::accumulator, 16, 16, 16, float> acc[4][2];
    #pragma unroll
    for (int i = 0; i < 4; i++)
        #pragma unroll
        for (int j = 0; j < 2; j++)
            wmma::fill_fragment(acc[i][j], 0.0f);

    // stage loader: 2048 16B chunks (4 arrays x 128 rows x 4 chunks), 8 per thread
    auto load_stage = [&](int s, int k0) {
        #pragma unroll
        for (int i = 0; i < 8; i++) {
            int cid  = tid + i * 256;
            int which = cid >> 9;          // 0:Ah 1:Al 2:Wh 3:Wl (uniform per i)
            int rem  = cid & 511;
            int row  = rem >> 2;
            int c8   = (rem & 3) * 8;
            const __nv_bfloat16* src;
            if      (which == 0) src = Ah + (size_t)(m0 + row) * K + k0 + c8;
            else if (which == 1) src = Al + (size_t)(m0 + row) * K + k0 + c8;
            else if (which == 2) src = Wh + (size_t)(n0 + row) * K + k0 + c8;
            else                 src = Wl + (size_t)(n0 + row) * K + k0 + c8;
            cp_async16(sm + (s * 4 + which) * TILE + row * GLD + c8, src);
        }
    };

    load_stage(0, 0);
    cp_commit();

    const int NKT = K / BK;   // 16
    for (int kt = 0; kt < NKT; kt++) {
        if (kt + 1 < NKT) {
            load_stage((kt + 1) & 1, (kt + 1) * BK);
            cp_commit();
            cp_wait1();
        } else {
            cp_wait0();
        }
        __syncthreads();

        const __nv_bfloat16* pAh = sm + ((kt & 1) * 4 + 0) * TILE;
        const __nv_bfloat16* pAl = sm + ((kt & 1) * 4 + 1) * TILE;
        const __nv_bfloat16* pWh = sm + ((kt & 1) * 4 + 2) * TILE;
        const __nv_bfloat16* pWl = sm + ((kt & 1) * 4 + 3) * TILE;

        #pragma unroll
        for (int kk = 0; kk < BK; kk += 16) {
            wmma::fragment<wmma::matrix_b, 16, 16, 16, __nv_bfloat16, wmma::col_major> bh[2], bl[2];
            #pragma unroll
            for (int nf = 0; nf < 2; nf++) {
                wmma::load_matrix_sync(bh[nf], pWh + (wn * 32 + nf * 16) * GLD + kk, GLD);
                wmma::load_matrix_sync(bl[nf], pWl + (wn * 32 + nf * 16) * GLD + kk, GLD);
            }
            #pragma unroll
            for (int mf = 0; mf < 4; mf++) {
                wmma::fragment<wmma::matrix_a, 16, 16, 16, __nv_bfloat16, wmma::row_major> ah, al;
                wmma::load_matrix_sync(ah, pAh + (wm * 64 + mf * 16) * GLD + kk, GLD);
                wmma::load_matrix_sync(al, pAl + (wm * 64 + mf * 16) * GLD + kk, GLD);
                #pragma unroll
                for (int nf = 0; nf < 2; nf++) {
                    wmma::mma_sync(acc[mf][nf], ah, bh[nf], acc[mf][nf]);
                    wmma::mma_sync(acc[mf][nf], ah, bl[nf], acc[mf][nf]);
                    wmma::mma_sync(acc[mf][nf], al, bh[nf], acc[mf][nf]);
                }
            }
        }
        __syncthreads();
    }

    // Epilogue via smem roundtrip
    float* scr   = (float*)sm;
    float* myscr = scr + w * 320;
    #pragma unroll
    for (int mf = 0; mf < 4; mf++) {
        #pragma unroll
        for (int nf = 0; nf < 2; nf++) {
            wmma::store_matrix_sync(myscr, acc[mf][nf], 20, wmma::mem_row_major);
            __syncwarp();
            #pragma unroll
            for (int e = 0; e < 8; e++) {
                int idx = e * 32 + lane;
                int r = idx >> 4, c = idx & 15;
                int row = m0 + wm * 64 + mf * 16 + r;
                int col = n0 + wn * 32 + nf * 16 + c;
                float v = myscr[r * 20 + c] + __ldg(&bias[col]);
                if (RELU) v = fmaxf(v, 0.0f);
                if (OUTPAIR) {
                    __nv_bfloat16 hi, lo; split_bf16(v, hi, lo);
                    Ch[(size_t)row * N + col] = hi;
                    Cl[(size_t)row * N + col] = lo;
                } else {
                    Cf[(size_t)row * N + col] = v;
                }
            }
            __syncwarp();
        }
    }
}

// =================================================================================
// Persistent GRU scan v3:
//  - hidden state exchanged as bf16 hi/lo PAIR in global -> stage is pure cp.async
//  - exact-h term reconstructed as hi+lo from smem (no fp32 round trip)
//  - register-resident weight fragments; 2-deep gi prefetch; tight acquire spin
//  - outputs layer activations directly as bf16 pair (feeds next GEMM)
// =================================================================================
#define SW        520
#define NBLK      32
#define GROUPS    4
#define BG        16
#define NTHR      384
#define SCAN_SMEM 50048

typedef wmma::fragment<wmma::matrix_b, 16, 16, 16, __nv_bfloat16, wmma::col_major> bfrag_t;
typedef wmma::fragment<wmma::matrix_a, 16, 16, 16, __nv_bfloat16, wmma::row_major> afrag_t;

__global__ __launch_bounds__(NTHR)
void scan_kernel(const float* __restrict__ gi, const float* __restrict__ whh,
                 const float* __restrict__ bhh,
                 __nv_bfloat16* __restrict__ ysh, __nv_bfloat16* __restrict__ ysl)
{
    extern __shared__ char smem_raw[];
    __nv_bfloat16* wtmp = (__nv_bfloat16*)smem_raw;        // init alias: 48 x SW
    __nv_bfloat16* hh = (__nv_bfloat16*)smem_raw;          // steady: 16 x SW
    __nv_bfloat16* hl = hh + 16 * SW;                      // 16 x SW
    float* gh  = (float*)(hl + 16 * SW);                   // [4][16][48]
    float* sbh = gh + 4 * 768;                             // 48

    const int tid   = threadIdx.x;
    const int g     = blockIdx.x >> 5;
    const int blk   = blockIdx.x & 31;
    const int c0    = blk * 16;
    const int w     = tid >> 5;
    const int ntile = w % 3;
    const int kq    = w / 3;
    const int bbase = g * BG;
    int* bar = &g_bar[g * 32];

    // ---- init: weight fragments into registers (hi pass, lo pass) ----
    bfrag_t bhf[8], blf[8];
    for (int i = tid; i < 48 * H_; i += NTHR) {
        int rl = i >> 9, k = i & 511;
        int grow = (rl >> 4) * H_ + c0 + (rl & 15);
        wtmp[rl * SW + k] = __float2bfloat16(whh[(size_t)grow * H_ + k]);
    }
    __syncthreads();
    #pragma unroll
    for (int i = 0; i < 8; i++)
        wmma::load_matrix_sync(bhf[i], wtmp + ntile * 16 * SW + kq * 128 + i * 16, SW);
    __syncthreads();
    for (int i = tid; i < 48 * H_; i += NTHR) {
        int rl = i >> 9, k = i & 511;
        int grow = (rl >> 4) * H_ + c0 + (rl & 15);
        float v = whh[(size_t)grow * H_ + k];
        wtmp[rl * SW + k] = __float2bfloat16(v - __bfloat162float(__float2bfloat16(v)));
    }
    __syncthreads();
    #pragma unroll
    for (int i = 0; i < 8; i++)
        wmma::load_matrix_sync(blf[i], wtmp + ntile * 16 * SW + kq * 128 + i * 16, SW);
    __syncthreads();
    if (tid < 48)
        sbh[tid] = bhh[(tid >> 4) * H_ + c0 + (tid & 15)];
    __syncthreads();

    // gi prefetch, 2 deep: a = t, b = t+1
    float a_r = 0.f, a_z = 0.f, a_n = 0.f, b_r = 0.f, b_z = 0.f, b_n = 0.f;
    const float* gbase = gi + (size_t)(bbase + (tid >> 4)) * T_ * G3H + (c0 + (tid & 15));
    if (tid < 256) {
        a_r = __ldg(gbase);            a_z = __ldg(gbase + H_);            a_n = __ldg(gbase + 2 * H_);
        b_r = __ldg(gbase + G3H);      b_z = __ldg(gbase + G3H + H_);      b_n = __ldg(gbase + G3H + 2 * H_);
    }

    for (int t = 0; t < T_; t++) {
        const int cur = t & 1, nxt = cur ^ 1;
        const __nv_bfloat16* srcH = g_hbH + cur * (B_ * H_);
        const __nv_bfloat16* srcL = g_hbL + cur * (B_ * H_);

        // Stage h pair [16 x 512] via pure cp.async (2048 16B chunks, ~5.3/thread)
        for (int i = tid; i < 2048; i += NTHR) {
            int which = i >> 10;
            int rem = i & 1023;
            int row = rem >> 6;
            int c8  = (rem & 63) * 8;
            const __nv_bfloat16* src = (which ? srcL : srcH) + (size_t)(bbase + row) * H_ + c8;
            __nv_bfloat16* dst = (which ? hl : hh) + row * SW + c8;
            cp_async16(dst, src);
        }
        cp_commit();
        cp_wait0();
        __syncthreads();

        // gh partial[kq][16 x 48]: register-resident weights
        {
            wmma::fragment<wmma::accumulator, 16, 16, 16, float> acc;
            wmma::fill_fragment(acc, 0.0f);
            const int kbase = kq * 128;
            afrag_t ah, al;
            #pragma unroll
            for (int i = 0; i < 8; i++) {
                int k = kbase + i * 16;
                wmma::load_matrix_sync(ah, hh + k, SW);
                wmma::load_matrix_sync(al, hl + k, SW);
                wmma::mma_sync(acc, ah, bhf[i], acc);
                wmma::mma_sync(acc, ah, blf[i], acc);
                wmma::mma_sync(acc, al, bhf[i], acc);
            }
            wmma::store_matrix_sync(gh + kq * 768 + ntile * 16, acc, 48, wmma::mem_row_major);
        }
        __syncthreads();

        // Gate epilogue: 256 elements
        if (tid < 256) {
            int b = tid >> 4, j = tid & 15;
            int c = c0 + j;
            size_t rowoff = (size_t)(bbase + b) * T_ + t;
            int o = b * 48 + j;
            float gr = gh[o]      + gh[768 + o]      + gh[1536 + o]      + gh[2304 + o]      + sbh[j];
            float gz = gh[o + 16] + gh[768 + o + 16] + gh[1536 + o + 16] + gh[2304 + o + 16] + sbh[16 + j];
            float gn = gh[o + 32] + gh[768 + o + 32] + gh[1536 + o + 32] + gh[2304 + o + 32] + sbh[32 + j];
            float ho = __bfloat162float(hh[b * SW + c]) + __bfloat162float(hl[b * SW + c]);
            float r = fast_sigmoid(a_r + gr);
            float z = fast_sigmoid(a_z + gz);
            float n = fast_tanh(a_n + r * gn);
            float hn = (1.0f - z) * n + z * ho;
            __nv_bfloat16 hi, lo; split_bf16(hn, hi, lo);
            ysh[rowoff * H_ + c] = hi;
            ysl[rowoff * H_ + c] = lo;
            size_t hoff = (size_t)nxt * (B_ * H_) + (size_t)(bbase + b) * H_ + c;
            g_hbH[hoff] = hi;
            g_hbL[hoff] = lo;
        }

        // rotate prefetch: a <- b, issue t+2 into b
        if (tid < 256) {
            a_r = b_r; a_z = b_z; a_n = b_n;
            if (t + 2 < T_) {
                const float* gp = gbase + (size_t)(t + 2) * G3H;
                b_r = __ldg(gp);
                b_z = __ldg(gp + H_);
                b_n = __ldg(gp + 2 * H_);
            }
        }

        __syncthreads();   // order h' stores before release
        if (tid == 0) {
            asm volatile("red.release.gpu.global.add.s32 [%0], 1;" :: "l"(bar) : "memory");
            const int target = NBLK * (t + 1);
            int v;
            do {
                asm volatile("ld.acquire.gpu.global.s32 %0, [%1];" : "=r"(v) : "l"(bar));
            } while (v < target);
        }
        __syncthreads();
    }
}

// =================================================================================
// Orchestration
// =================================================================================
extern "C" void kernel_launch(void* const* d_in, const int* in_sizes, int n_in,
                              void* d_out, int out_size)
{
    const float* x    = (const float*)d_in[0];
    const float* w_in = (const float*)d_in[1];
    const float* b_in = (const float*)d_in[2];
    const float* w_ih = (const float*)d_in[3];
    const float* w_hh = (const float*)d_in[4];
    const float* b_ih = (const float*)d_in[5];
    const float* b_hh = (const float*)d_in[6];
    const float* w_o1 = (const float*)d_in[7];
    const float* b_o1 = (const float*)d_in[8];
    const float* w_o2 = (const float*)d_in[9];
    const float* b_o2 = (const float*)d_in[10];
    float* out = (float*)d_out;
    (void)in_sizes; (void)n_in; (void)out_size;

    float *gi; __nv_bfloat16 *aAh, *aAl, *aBh, *aBl, *wh, *wl, *hbH, *hbL; int* bar;
    cudaGetSymbolAddress((void**)&gi,  g_gi);
    cudaGetSymbolAddress((void**)&aAh, g_aAh);
    cudaGetSymbolAddress((void**)&aAl, g_aAl);
    cudaGetSymbolAddress((void**)&aBh, g_aBh);
    cudaGetSymbolAddress((void**)&aBl, g_aBl);
    cudaGetSymbolAddress((void**)&wh,  g_wh);
    cudaGetSymbolAddress((void**)&wl,  g_wl);
    cudaGetSymbolAddress((void**)&hbH, g_hbH);
    cudaGetSymbolAddress((void**)&hbL, g_hbL);
    cudaGetSymbolAddress((void**)&bar, g_bar);

    cudaFuncSetAttribute(scan_kernel, cudaFuncAttributeMaxDynamicSharedMemorySize, SCAN_SMEM);
    cudaFuncSetAttribute(gemm2<1,1>, cudaFuncAttributeMaxDynamicSharedMemorySize, GEMM_SMEM);
    cudaFuncSetAttribute(gemm2<0,0>, cudaFuncAttributeMaxDynamicSharedMemorySize, GEMM_SMEM);

    // ---- pre-split inputs and weights to bf16 pairs ----
    split_kernel<<<(M_ * H_ / 4 + 255) / 256, 256>>>(x, aAh, aAl, M_ * H_ / 4);
    split_kernel<<<(512 * 512 / 4 + 255) / 256, 256>>>(w_in, wh + OFF_WIN, wl + OFF_WIN, 512 * 512 / 4);
    split_kernel<<<(4 * G3H * H_ / 4 + 255) / 256, 256>>>(w_ih, wh + OFF_WIH, wl + OFF_WIH, 4 * G3H * H_ / 4);
    split_kernel<<<(512 * 512 / 4 + 255) / 256, 256>>>(w_o1, wh + OFF_WO1, wl + OFF_WO1, 512 * 512 / 4);
    split_kernel<<<(512 * 512 / 4 + 255) / 256, 256>>>(w_o2, wh + OFF_WO2, wl + OFF_WO2, 512 * 512 / 4);

    // input Linear + ReLU -> pair B
    gemm2<1,1><<<dim3(H_ / BN, M_ / BM), 256, GEMM_SMEM>>>(
        aAh, aAl, wh + OFF_WIN, wl + OFF_WIN, b_in, nullptr, aBh, aBl, M_, H_, H_);

    __nv_bfloat16 *curh = aBh, *curl = aBl, *oth = aAh, *otl = aAl;
    for (int l = 0; l < L_; l++) {
        gemm2<0,0><<<dim3(G3H / BN, M_ / BM), 256, GEMM_SMEM>>>(
            curh, curl, wh + OFF_WIH + (size_t)l * G3H * H_, wl + OFF_WIH + (size_t)l * G3H * H_,
            b_ih + (size_t)l * G3H, gi, nullptr, nullptr, M_, G3H, H_);
        cudaMemsetAsync(hbH, 0, sizeof(__nv_bfloat16) * 2 * B_ * H_);
        cudaMemsetAsync(hbL, 0, sizeof(__nv_bfloat16) * 2 * B_ * H_);
        cudaMemsetAsync(bar, 0, sizeof(int) * 4 * 32);
        scan_kernel<<<NBLK * GROUPS, NTHR, SCAN_SMEM>>>(
            gi, w_hh + (size_t)l * G3H * H_, b_hh + (size_t)l * G3H, oth, otl);
        __nv_bfloat16* t1 = curh; curh = oth; oth = t1;
        __nv_bfloat16* t2 = curl; curl = otl; otl = t2;
    }

    // output MLP: o1 (ReLU, pair) then o2 (fp32 -> d_out)
    gemm2<1,1><<<dim3(H_ / BN, M_ / BM), 256, GEMM_SMEM>>>(
        curh, curl, wh + OFF_WO1, wl + OFF_WO1, b_o1, nullptr, oth, otl, M_, H_, H_);
    gemm2<0,0><<<dim3(H_ / BN, M_ / BM), 256, GEMM_SMEM>>>(
        oth, otl, wh + OFF_WO2, wl + OFF_WO2, b_o2, out, nullptr, nullptr, M_, H_, H_);
}